// round 6
// baseline (speedup 1.0000x reference)
#include <cuda_runtime.h>

#define NB 32
#define NC 3
#define NH 256
#define NW 256
#define KS 29
#define PADK 14
#define HID 32
#define TY 16
#define TX 16
#define HW (NH*NW)
#define NPIX (NB*NC*NH*NW)
#define NBLK (NB*(NH/TY)*(NW/TX))   // 8192

typedef unsigned long long u64t;

__device__ float g_z2[NB*NC*HW];
__device__ float g_partials[NBLK];
__device__ int   g_done = 0;

// packed weight staging (device) -> copied into __constant__
__device__ ulonglong2 g_w1s[HID*14];     // [o][j2]: .x={w2j,w2j}, .y={w2j+1,w2j+1}
__device__ ulonglong2 g_w2s[27*8];       // [(co*9+tap)*8+og]: .x=(o0,o1) .y=(o2,o3)
__device__ float      g_miscs[67];       // b1[32] tw[32] b2[3]

__constant__ ulonglong2 c_w1[HID*14];
__constant__ ulonglong2 c_w2[27*8];
__constant__ float      c_misc[67];

// ---------------- packed f32x2 helpers (sm_103a) ----------------
__device__ __forceinline__ u64t pk2(float a, float b) {
    u64t r; asm("mov.b64 %0, {%1,%2};" : "=l"(r) : "f"(a), "f"(b)); return r;
}
__device__ __forceinline__ void upk2(u64t v, float& a, float& b) {
    asm("mov.b64 {%0,%1}, %2;" : "=f"(a), "=f"(b) : "l"(v));
}
__device__ __forceinline__ u64t fma2(u64t a, u64t b, u64t c) {
    u64t d; asm("fma.rn.f32x2 %0, %1, %2, %3;" : "=l"(d) : "l"(a), "l"(b), "l"(c));
    return d;
}
__device__ __forceinline__ void lds2u64(unsigned s, u64t& a, u64t& b) {
    asm volatile("ld.shared.v2.u64 {%0,%1}, [%2];" : "=l"(a), "=l"(b) : "r"(s));
}
__device__ __forceinline__ void sts4f(unsigned s, float a, float b, float c, float d) {
    asm volatile("st.shared.v4.f32 [%0], {%1,%2,%3,%4};" :: "r"(s), "f"(a), "f"(b), "f"(c), "f"(d));
}

// ---------------------------------------------------------------------------
// 0) pack weights into f32x2-friendly layouts (then memcpy'd to __constant__)
// ---------------------------------------------------------------------------
__global__ void pack_kernel(const float* __restrict__ W1,
                            const float* __restrict__ b1,
                            const float* __restrict__ tw,
                            const float* __restrict__ W2,
                            const float* __restrict__ b2) {
    int tid = threadIdx.x;
    for (int i = tid; i < HID*14; i += 256) {
        int o = i / 14, j2 = i % 14;
        int j0 = 2*j2, j1 = j0 + 1;
        float a = (j0 < 27) ? W1[o*27 + j0] : 0.f;
        float b = (j1 < 27) ? W1[o*27 + j1] : 0.f;
        ulonglong2 v; v.x = pk2(a, a); v.y = pk2(b, b);
        g_w1s[i] = v;
    }
    for (int i = tid; i < 27*8; i += 256) {
        int og = i & 7, rem = i >> 3;      // rem = co*9+tap
        int tap = rem % 9, co = rem / 9;
        int o0 = og * 4;
        ulonglong2 v;
        v.x = pk2(W2[co*288 + o0*9 + tap],     W2[co*288 + (o0+1)*9 + tap]);
        v.y = pk2(W2[co*288 + (o0+2)*9 + tap], W2[co*288 + (o0+3)*9 + tap]);
        g_w2s[i] = v;
    }
    if (tid < HID) { g_miscs[tid] = b1[tid]; g_miscs[HID+tid] = tw[tid]; }
    if (tid < 3)   g_miscs[64+tid] = b2[tid];
}

// ---------------------------------------------------------------------------
// 1) fused separable blur (reflect), f32x2 packed. One block = 32-row strip.
//    smem: xin[60][256] | vt[32][257] | kk[32]; hout reuses xin (stride 257)
// ---------------------------------------------------------------------------
#define BXIN 0
#define BVT  15360
#define BKK  23584
#define BLUR_SMEM ((23584 + 32) * 4)

__global__ __launch_bounds__(256, 2)
void blur_kernel(const float* __restrict__ x,
                 const int* __restrict__ t,
                 const float* __restrict__ sched) {
    extern __shared__ float s[];
    float* xin  = s + BXIN;
    float* vt   = s + BVT;
    float* kk   = s + BKK;
    float* hout = s + BXIN;

    int bc = blockIdx.y;
    int b  = bc / NC;
    int y0 = blockIdx.x * 32;
    int tid = threadIdx.x;

    // in-block gaussian taps (warp 0)
    if (tid < 32) {
        float sigma = sched[t[b]];
        float val = 0.f;
        if (tid < KS) {
            float xg = (float)(tid - PADK) / sigma;
            val = expf(-0.5f * xg * xg);
        }
        float ssum = val;
#pragma unroll
        for (int off = 16; off; off >>= 1)
            ssum += __shfl_xor_sync(0xffffffffu, ssum, off);
        if (tid < KS) kk[tid] = val / ssum;
    }

    const float* src = x + (size_t)bc * HW;
    int c4 = (tid & 63) * 4;
    for (int i = tid >> 6; i < 60; i += 4) {
        int gy = y0 - PADK + i;
        gy = gy < 0 ? -gy : (gy > NH-1 ? 2*(NH-1) - gy : gy);
        *(float4*)&xin[i*256 + c4] = *(const float4*)&src[gy*NW + c4];
    }
    __syncthreads();

    // vertical: 2 adjacent columns per thread packed in f32x2
    {
        u64t kv[KS];
#pragma unroll
        for (int k = 0; k < KS; k++) kv[k] = pk2(kk[k], kk[k]);
        int cp = tid & 127, half = tid >> 7;
#pragma unroll 1
        for (int c2 = 0; c2 < 2; c2++) {
            int cr = (half*2 + c2) * 8;
            u64t acc[8] = {0,0,0,0,0,0,0,0};
#pragma unroll
            for (int i = 0; i < 36; i++) {
                u64t v = *(const u64t*)&xin[(cr + i)*256 + 2*cp];
#pragma unroll
                for (int a = 0; a < 8; a++) {
                    int k = i - a;
                    if (k >= 0 && k < KS) acc[a] = fma2(kv[k], v, acc[a]);
                }
            }
#pragma unroll
            for (int a = 0; a < 8; a++) {
                float lo, hi; upk2(acc[a], lo, hi);
                vt[(cr + a)*257 + 2*cp]     = lo;
                vt[(cr + a)*257 + 2*cp + 1] = hi;
            }
        }
    }
    __syncthreads();

    // horizontal: 16 output cols per task (8 output-pairs packed in f32x2)
    {
        u64t kh[KS+1];
        kh[0]  = pk2(kk[0], 0.f);
#pragma unroll
        for (int m = 1; m < KS; m++) kh[m] = pk2(kk[m], kk[m-1]);
        kh[KS] = pk2(0.f, kk[KS-1]);
#pragma unroll 1
        for (int it = 0; it < 2; it++) {
            int task = tid + it*256;
            int rr = task & 31, cs = (task >> 5) * 16;
            u64t acc[8] = {0,0,0,0,0,0,0,0};
#pragma unroll
            for (int i = 0; i < 44; i++) {
                int col = cs - PADK + i;
                col = col < 0 ? -col : (col > NW-1 ? 2*(NW-1) - col : col);
                float v = vt[rr*257 + col];
                u64t vv = pk2(v, v);
#pragma unroll
                for (int a = 0; a < 8; a++) {
                    int m = i - 2*a;
                    if (m >= 0 && m <= KS) acc[a] = fma2(kh[m], vv, acc[a]);
                }
            }
#pragma unroll
            for (int a = 0; a < 8; a++) {
                float lo, hi; upk2(acc[a], lo, hi);
                hout[rr*257 + cs + 2*a]     = lo;
                hout[rr*257 + cs + 2*a + 1] = hi;
            }
        }
    }
    __syncthreads();

    float* dst = g_z2 + (size_t)bc * HW + (size_t)y0 * NW;
#pragma unroll 1
    for (int r2 = 0; r2 < 32; r2++)
        dst[r2*NW + tid] = hout[r2*257 + tid];
}

// ---------------------------------------------------------------------------
// 2) fused conv1+relu+conv2+loss, weights in __constant__ (LDCU, no crossbar)
//    smem floats: hs[11664] @0 | zs[1200] @11664  -> 12864 floats (51456 B)
// ---------------------------------------------------------------------------
#define CHS 0
#define CZS 11664
#define CONV_SMEM (12864 * 4)

__global__ __launch_bounds__(256, 3)
void conv_loss_kernel(const float* __restrict__ x,
                      const int* __restrict__ t,
                      float* __restrict__ out) {
    extern __shared__ float sm[];
    float* hs = sm + CHS;
    float* zs = sm + CZS;

    unsigned smem_u = (unsigned)__cvta_generic_to_shared(sm);
    int tid = threadIdx.x;
    int bx = blockIdx.x, by = blockIdx.y, b = blockIdx.z;
    int x0 = bx*TX, y0 = by*TY;

    float tn = (float)t[b] * (1.0f / 1000.0f);

    // z tile with halo 2
    const float* zsrc = g_z2 + (size_t)b*NC*HW;
    for (int i = tid; i < NC*20*20; i += 256) {
        int ch = i / 400, rr = (i / 20) % 20, cc = i % 20;
        int gy = y0 - 2 + rr, gx = x0 - 2 + cc;
        float v = 0.f;
        if ((unsigned)gy < NH && (unsigned)gx < NW)
            v = zsrc[ch*HW + gy*NW + gx];
        zs[i] = v;
    }
    __syncthreads();

    // conv1: 162 threads x 2 positions packed in f32x2, weights via constant
    if (tid < 162) {
        int p0 = tid, p1 = tid + 162;
        int r0 = p0/18, c0 = p0%18, r1 = p1/18, c1 = p1%18;
        u64t pz[28];
#pragma unroll
        for (int ch = 0; ch < 3; ch++)
#pragma unroll
            for (int ky = 0; ky < 3; ky++)
#pragma unroll
                for (int kx = 0; kx < 3; kx++) {
                    int j = ch*9 + ky*3 + kx;
                    pz[j] = pk2(zs[ch*400 + (r0+ky)*20 + (c0+kx)],
                                zs[ch*400 + (r1+ky)*20 + (c1+kx)]);
                }
        pz[27] = 0ULL;
        int gy0 = y0-1+r0, gx0 = x0-1+c0, gy1 = y0-1+r1, gx1 = x0-1+c1;
        bool in0 = (unsigned)gy0 < NH && (unsigned)gx0 < NW;
        bool in1 = (unsigned)gy1 < NH && (unsigned)gx1 < NW;

        unsigned hs0 = smem_u + (unsigned)(p0*36)*4;
        unsigned hs1 = smem_u + (unsigned)(p1*36)*4;
#pragma unroll 1
        for (int og = 0; og < 8; og++) {
            float s0[4], s1[4];
#pragma unroll
            for (int oi = 0; oi < 4; oi++) {
                int o = og*4 + oi;
                float base = fmaf(tn, c_misc[HID + o], c_misc[o]);
                u64t acc = pk2(base, base);
#pragma unroll
                for (int j2 = 0; j2 < 14; j2++) {
                    ulonglong2 w = c_w1[o*14 + j2];
                    acc = fma2(w.x, pz[2*j2],   acc);
                    acc = fma2(w.y, pz[2*j2+1], acc);
                }
                float lo, hi; upk2(acc, lo, hi);
                s0[oi] = in0 ? fmaxf(lo, 0.f) : 0.f;
                s1[oi] = in1 ? fmaxf(hi, 0.f) : 0.f;
            }
            sts4f(hs0 + og*16, s0[0], s0[1], s0[2], s0[3]);
            sts4f(hs1 + og*16, s1[0], s1[1], s1[2], s1[3]);
        }
    }
    __syncthreads();

    // conv2: 128 threads, 2 vertical pixels, o packed in f32x2, const weights
    float e = 0.f;
    if (tid < 128) {
        int c = tid & 15, r = (tid >> 4) * 2;
        u64t a0[3] = {0,0,0}, a1[3] = {0,0,0};
        unsigned hbase = smem_u + (unsigned)((r*18 + c)*36)*4;
#pragma unroll 1
        for (int og = 0; og < 8; og++) {
#pragma unroll
            for (int kx = 0; kx < 3; kx++) {
                u64t h[4][2];
#pragma unroll
                for (int u = 0; u < 4; u++)
                    lds2u64(hbase + (unsigned)((u*18 + kx)*36)*4 + og*16,
                            h[u][0], h[u][1]);
#pragma unroll
                for (int co = 0; co < 3; co++)
#pragma unroll
                    for (int ky = 0; ky < 3; ky++) {
                        ulonglong2 w = c_w2[(co*9 + ky*3 + kx)*8 + og];
                        a0[co] = fma2(w.x, h[ky][0],   a0[co]);
                        a0[co] = fma2(w.y, h[ky][1],   a0[co]);
                        a1[co] = fma2(w.x, h[ky+1][0], a1[co]);
                        a1[co] = fma2(w.y, h[ky+1][1], a1[co]);
                    }
            }
        }
        int gy = y0 + r, gx = x0 + c;
        const float* xb = x + (size_t)b*NC*HW + gy*NW + gx;
#pragma unroll
        for (int co = 0; co < 3; co++) {
            float lo, hi;
            upk2(a0[co], lo, hi); float pr0 = lo + hi + c_misc[64+co];
            upk2(a1[co], lo, hi); float pr1 = lo + hi + c_misc[64+co];
            float d0 = xb[co*HW]      - pr0;
            float d1 = xb[co*HW + NW] - pr1;
            e += d0*d0 + d1*d1;
        }
    }

    // block reduce
#pragma unroll
    for (int off = 16; off; off >>= 1) e += __shfl_down_sync(0xffffffffu, e, off);
    float* wsum = zs;   // zs free after conv1
    __syncthreads();
    if ((tid & 31) == 0) wsum[tid >> 5] = e;
    __syncthreads();
    __shared__ int s_last;
    if (tid == 0) {
        float v = wsum[0]+wsum[1]+wsum[2]+wsum[3]+wsum[4]+wsum[5]+wsum[6]+wsum[7];
        g_partials[(b*16 + by)*16 + bx] = v;
        __threadfence();
        int old = atomicAdd(&g_done, 1);
        s_last = (old == NBLK - 1);
    }
    __syncthreads();

    // last block folds the final mean (deterministic: fixed summation order)
    if (s_last) {
        double acc = 0.0;
        for (int i = tid; i < NBLK; i += 256) acc += (double)g_partials[i];
        double* sh = (double*)sm;
        sh[tid] = acc;
        __syncthreads();
        for (int s2 = 128; s2; s2 >>= 1) {
            if (tid < s2) sh[tid] += sh[tid + s2];
            __syncthreads();
        }
        if (tid == 0) {
            out[0] = (float)(sh[0] / (double)NPIX);
            g_done = 0;
        }
    }
}

// ---------------------------------------------------------------------------
extern "C" void kernel_launch(void* const* d_in, const int* in_sizes, int n_in,
                              void* d_out, int out_size) {
    const float* x     = (const float*)d_in[0];
    const int*   t     = (const int*)  d_in[1];
    const float* W1    = (const float*)d_in[2];
    const float* b1    = (const float*)d_in[3];
    const float* tw    = (const float*)d_in[4];
    const float* W2    = (const float*)d_in[5];
    const float* b2    = (const float*)d_in[6];
    const float* sched = (const float*)d_in[7];

    pack_kernel<<<1, 256>>>(W1, b1, tw, W2, b2);

    void *pw1, *pw2, *pmisc;
    cudaGetSymbolAddress(&pw1,  g_w1s);
    cudaGetSymbolAddress(&pw2,  g_w2s);
    cudaGetSymbolAddress(&pmisc, g_miscs);
    cudaMemcpyToSymbolAsync(c_w1,  pw1,  sizeof(ulonglong2)*HID*14, 0,
                            cudaMemcpyDeviceToDevice, 0);
    cudaMemcpyToSymbolAsync(c_w2,  pw2,  sizeof(ulonglong2)*27*8, 0,
                            cudaMemcpyDeviceToDevice, 0);
    cudaMemcpyToSymbolAsync(c_misc, pmisc, sizeof(float)*67, 0,
                            cudaMemcpyDeviceToDevice, 0);

    cudaFuncSetAttribute(blur_kernel,
                         cudaFuncAttributeMaxDynamicSharedMemorySize, BLUR_SMEM);
    blur_kernel<<<dim3(NH/32, NB*NC), 256, BLUR_SMEM>>>(x, t, sched);

    cudaFuncSetAttribute(conv_loss_kernel,
                         cudaFuncAttributeMaxDynamicSharedMemorySize, CONV_SMEM);
    conv_loss_kernel<<<dim3(NW/TX, NH/TY, NB), 256, CONV_SMEM>>>(x, t, (float*)d_out);
}

// round 10
// speedup vs baseline: 1.6055x; 1.6055x over previous
#include <cuda_runtime.h>

#define NB 32
#define NC 3
#define NH 256
#define NW 256
#define KS 29
#define PADK 14
#define HID 32
#define TY 16
#define TX 16
#define HW (NH*NW)
#define NPIX (NB*NC*NH*NW)
#define NBLK (NB*(NH/TY)*(NW/TX))   // 8192

typedef unsigned long long u64t;

__device__ float g_z2[NB*NC*HW];
__device__ float g_partials[NBLK];
__device__ int   g_done = 0;

// ---------------- packed f32x2 helpers (sm_103a) ----------------
__device__ __forceinline__ u64t pk2(float a, float b) {
    u64t r; asm("mov.b64 %0, {%1,%2};" : "=l"(r) : "f"(a), "f"(b)); return r;
}
__device__ __forceinline__ void upk2(u64t v, float& a, float& b) {
    asm("mov.b64 {%0,%1}, %2;" : "=f"(a), "=f"(b) : "l"(v));
}
__device__ __forceinline__ u64t fma2(u64t a, u64t b, u64t c) {
    u64t d; asm("fma.rn.f32x2 %0, %1, %2, %3;" : "=l"(d) : "l"(a), "l"(b), "l"(c));
    return d;
}
__device__ __forceinline__ void lds2u64(unsigned s, u64t& a, u64t& b) {
    asm volatile("ld.shared.v2.u64 {%0,%1}, [%2];" : "=l"(a), "=l"(b) : "r"(s));
}
__device__ __forceinline__ void sts4f(unsigned s, float a, float b, float c, float d) {
    asm volatile("st.shared.v4.f32 [%0], {%1,%2,%3,%4};" :: "r"(s), "f"(a), "f"(b), "f"(c), "f"(d));
}

// ---------------------------------------------------------------------------
// 1) fused separable blur (reflect), f32x2 packed, taps computed in-block.
// ---------------------------------------------------------------------------
#define BXIN 0
#define BVT  15360
#define BKK  23584
#define BLUR_SMEM ((23584 + 32) * 4)

__global__ __launch_bounds__(256, 2)
void blur_kernel(const float* __restrict__ x,
                 const int* __restrict__ t,
                 const float* __restrict__ sched) {
    extern __shared__ float s[];
    float* xin  = s + BXIN;
    float* vt   = s + BVT;
    float* kk   = s + BKK;
    float* hout = s + BXIN;

    int bc = blockIdx.y;
    int b  = bc / NC;
    int y0 = blockIdx.x * 32;
    int tid = threadIdx.x;

    if (tid < 32) {
        float sigma = sched[t[b]];
        float val = 0.f;
        if (tid < KS) {
            float xg = (float)(tid - PADK) / sigma;
            val = expf(-0.5f * xg * xg);
        }
        float ssum = val;
#pragma unroll
        for (int off = 16; off; off >>= 1)
            ssum += __shfl_xor_sync(0xffffffffu, ssum, off);
        if (tid < KS) kk[tid] = val / ssum;
    }

    const float* src = x + (size_t)bc * HW;
    int c4 = (tid & 63) * 4;
    for (int i = tid >> 6; i < 60; i += 4) {
        int gy = y0 - PADK + i;
        gy = gy < 0 ? -gy : (gy > NH-1 ? 2*(NH-1) - gy : gy);
        *(float4*)&xin[i*256 + c4] = *(const float4*)&src[gy*NW + c4];
    }
    __syncthreads();

    // vertical: 2 adjacent columns per thread packed in f32x2
    {
        u64t kv[KS];
#pragma unroll
        for (int k = 0; k < KS; k++) kv[k] = pk2(kk[k], kk[k]);
        int cp = tid & 127, half = tid >> 7;
#pragma unroll 1
        for (int c2 = 0; c2 < 2; c2++) {
            int cr = (half*2 + c2) * 8;
            u64t acc[8] = {0,0,0,0,0,0,0,0};
#pragma unroll
            for (int i = 0; i < 36; i++) {
                u64t v = *(const u64t*)&xin[(cr + i)*256 + 2*cp];
#pragma unroll
                for (int a = 0; a < 8; a++) {
                    int k = i - a;
                    if (k >= 0 && k < KS) acc[a] = fma2(kv[k], v, acc[a]);
                }
            }
#pragma unroll
            for (int a = 0; a < 8; a++) {
                float lo, hi; upk2(acc[a], lo, hi);
                vt[(cr + a)*257 + 2*cp]     = lo;
                vt[(cr + a)*257 + 2*cp + 1] = hi;
            }
        }
    }
    __syncthreads();

    // horizontal: 16 output cols per task (8 output-pairs in f32x2)
    {
        u64t kh[KS+1];
        kh[0]  = pk2(kk[0], 0.f);
#pragma unroll
        for (int m = 1; m < KS; m++) kh[m] = pk2(kk[m], kk[m-1]);
        kh[KS] = pk2(0.f, kk[KS-1]);
#pragma unroll 1
        for (int it = 0; it < 2; it++) {
            int task = tid + it*256;
            int rr = task & 31, cs = (task >> 5) * 16;
            u64t acc[8] = {0,0,0,0,0,0,0,0};
#pragma unroll
            for (int i = 0; i < 44; i++) {
                int col = cs - PADK + i;
                col = col < 0 ? -col : (col > NW-1 ? 2*(NW-1) - col : col);
                float v = vt[rr*257 + col];
                u64t vv = pk2(v, v);
#pragma unroll
                for (int a = 0; a < 8; a++) {
                    int m = i - 2*a;
                    if (m >= 0 && m <= KS) acc[a] = fma2(kh[m], vv, acc[a]);
                }
            }
#pragma unroll
            for (int a = 0; a < 8; a++) {
                float lo, hi; upk2(acc[a], lo, hi);
                hout[rr*257 + cs + 2*a]     = lo;
                hout[rr*257 + cs + 2*a + 1] = hi;
            }
        }
    }
    __syncthreads();

    float* dst = g_z2 + (size_t)bc * HW + (size_t)y0 * NW;
#pragma unroll 1
    for (int r2 = 0; r2 < 32; r2++)
        dst[r2*NW + tid] = hout[r2*257 + tid];
}

// ---------------------------------------------------------------------------
// 2) fused conv1+relu+conv2+loss+final reduce.  Weights in SMEM (no LDC!).
//    smem floats: hs[11664] @0 | zs[1200] | ws1dup[1792] | ws2[864] | misc[72]
// ---------------------------------------------------------------------------
#define CHS   0
#define CZS   11664
#define CWS1  12864
#define CWS2  14656
#define CMISC 15520
#define CONV_SMEM (15616 * 4)

__global__ __launch_bounds__(256, 3)
void conv_loss_kernel(const float* __restrict__ x,
                      const int* __restrict__ t,
                      const float* __restrict__ W1,
                      const float* __restrict__ b1,
                      const float* __restrict__ tw,
                      const float* __restrict__ W2,
                      const float* __restrict__ b2,
                      float* __restrict__ out) {
    extern __shared__ float sm[];
    float* hs   = sm + CHS;
    float* zs   = sm + CZS;
    float* ws1  = sm + CWS1;
    float* ws2  = sm + CWS2;
    float* misc = sm + CMISC;

    unsigned smem_u = (unsigned)__cvta_generic_to_shared(sm);
    int tid = threadIdx.x;
    int bx = blockIdx.x, by = blockIdx.y, b = blockIdx.z;
    int x0 = bx*TX, y0 = by*TY;

    // weights -> smem (dup layout for conv1 f32x2; tap-major x32 for conv2)
    for (int i = tid; i < HID*NC*9; i += 256) {
        int o = i / 27, j = i % 27;
        float v = W1[i];
        ws1[o*56 + 2*j] = v;
        ws1[o*56 + 2*j + 1] = v;
    }
    if (tid < HID) { ws1[tid*56 + 54] = 0.f; ws1[tid*56 + 55] = 0.f; }
    for (int i = tid; i < NC*HID*9; i += 256) {
        int co = i / 288, rem = i % 288, o = rem / 9, tap = rem % 9;
        ws2[(co*9 + tap)*32 + o] = W2[i];
    }
    if (tid < HID) { misc[tid] = b1[tid]; misc[HID + tid] = tw[tid]; }
    float tn = (float)t[b] * (1.0f / 1000.0f);

    const float* zsrc = g_z2 + (size_t)b*NC*HW;
    for (int i = tid; i < NC*20*20; i += 256) {
        int ch = i / 400, rr = (i / 20) % 20, cc = i % 20;
        int gy = y0 - 2 + rr, gx = x0 - 2 + cc;
        float v = 0.f;
        if ((unsigned)gy < NH && (unsigned)gx < NW)
            v = zsrc[ch*HW + gy*NW + gx];
        zs[i] = v;
    }
    __syncthreads();

    // --- conv1: 162 threads x 2 positions packed in f32x2 ---
    if (tid < 162) {
        int p0 = tid, p1 = tid + 162;
        int r0 = p0/18, c0 = p0%18, r1 = p1/18, c1 = p1%18;
        u64t pz[28];
#pragma unroll
        for (int ch = 0; ch < 3; ch++)
#pragma unroll
            for (int ky = 0; ky < 3; ky++)
#pragma unroll
                for (int kx = 0; kx < 3; kx++) {
                    int j = ch*9 + ky*3 + kx;
                    pz[j] = pk2(zs[ch*400 + (r0+ky)*20 + (c0+kx)],
                                zs[ch*400 + (r1+ky)*20 + (c1+kx)]);
                }
        pz[27] = 0ULL;
        int gy0 = y0-1+r0, gx0 = x0-1+c0, gy1 = y0-1+r1, gx1 = x0-1+c1;
        bool in0 = (unsigned)gy0 < NH && (unsigned)gx0 < NW;
        bool in1 = (unsigned)gy1 < NH && (unsigned)gx1 < NW;

        unsigned ws1_s = smem_u + CWS1*4;
        unsigned hs0 = smem_u + (unsigned)(p0*36)*4;
        unsigned hs1 = smem_u + (unsigned)(p1*36)*4;
#pragma unroll 1
        for (int og = 0; og < 8; og++) {
            float s0[4], s1[4];
#pragma unroll
            for (int oi = 0; oi < 4; oi++) {
                int o = og*4 + oi;
                float base = fmaf(tn, misc[HID + o], misc[o]);
                u64t acc = pk2(base, base);
                unsigned wa = ws1_s + (unsigned)o*224;
#pragma unroll
                for (int j2 = 0; j2 < 14; j2++) {
                    u64t w0, w1;
                    lds2u64(wa + j2*16, w0, w1);
                    acc = fma2(w0, pz[2*j2],   acc);
                    acc = fma2(w1, pz[2*j2+1], acc);
                }
                float lo, hi; upk2(acc, lo, hi);
                s0[oi] = in0 ? fmaxf(lo, 0.f) : 0.f;
                s1[oi] = in1 ? fmaxf(hi, 0.f) : 0.f;
            }
            sts4f(hs0 + og*16, s0[0], s0[1], s0[2], s0[3]);
            sts4f(hs1 + og*16, s1[0], s1[1], s1[2], s1[3]);
        }
    }
    __syncthreads();

    // --- conv2: 64 threads, 2x2 pixels each; weights amortized over 4 px ---
    float e = 0.f;
    if (tid < 64) {
        int c = (tid & 7) * 2, r = (tid >> 3) * 2;
        u64t acc[2][2][3];
#pragma unroll
        for (int i = 0; i < 2; i++)
#pragma unroll
            for (int j = 0; j < 2; j++)
#pragma unroll
                for (int co = 0; co < 3; co++) acc[i][j][co] = 0ULL;

        unsigned wbase = smem_u + CWS2*4;
        // h addr for (row u, col j): pos = (r+u)*18 + (c+j); word pos*36+og*4
        unsigned hb = smem_u + (unsigned)((r*18 + c)*36)*4;
#pragma unroll 1
        for (int og = 0; og < 8; og++) {
            u64t hc[2][4][2];   // ring over columns: hc[j&1][row][pair]
#pragma unroll
            for (int u = 0; u < 4; u++) {
                lds2u64(hb + (unsigned)((u*18 + 0)*36)*4 + og*16, hc[0][u][0], hc[0][u][1]);
                lds2u64(hb + (unsigned)((u*18 + 1)*36)*4 + og*16, hc[1][u][0], hc[1][u][1]);
            }
#pragma unroll
            for (int kx = 0; kx < 3; kx++) {
                u64t (*h0)[2] = hc[kx & 1];          // col kx
                u64t (*h1)[2] = hc[(kx + 1) & 1];    // col kx+1
#pragma unroll
                for (int co = 0; co < 3; co++)
#pragma unroll
                    for (int ky = 0; ky < 3; ky++) {
                        u64t wx, wy;
                        lds2u64(wbase + (unsigned)((co*9 + ky*3 + kx)*8 + og)*16, wx, wy);
                        acc[0][0][co] = fma2(wx, h0[ky][0],   acc[0][0][co]);
                        acc[0][0][co] = fma2(wy, h0[ky][1],   acc[0][0][co]);
                        acc[0][1][co] = fma2(wx, h1[ky][0],   acc[0][1][co]);
                        acc[0][1][co] = fma2(wy, h1[ky][1],   acc[0][1][co]);
                        acc[1][0][co] = fma2(wx, h0[ky+1][0], acc[1][0][co]);
                        acc[1][0][co] = fma2(wy, h0[ky+1][1], acc[1][0][co]);
                        acc[1][1][co] = fma2(wx, h1[ky+1][0], acc[1][1][co]);
                        acc[1][1][co] = fma2(wy, h1[ky+1][1], acc[1][1][co]);
                    }
                // prefetch col kx+2 into the slot of col kx (not needed after)
                if (kx < 2) {
#pragma unroll
                    for (int u = 0; u < 4; u++)
                        lds2u64(hb + (unsigned)((u*18 + (kx+2))*36)*4 + og*16,
                                hc[kx & 1][u][0], hc[kx & 1][u][1]);
                }
            }
        }
        int gy = y0 + r, gx = x0 + c;
        const float* xb = x + (size_t)b*NC*HW + gy*NW + gx;
#pragma unroll
        for (int co = 0; co < 3; co++) {
            float bco = b2[co];
#pragma unroll
            for (int i = 0; i < 2; i++)
#pragma unroll
                for (int j = 0; j < 2; j++) {
                    float lo, hi; upk2(acc[i][j][co], lo, hi);
                    float pr = lo + hi + bco;
                    float d = xb[co*HW + i*NW + j] - pr;
                    e += d*d;
                }
        }
    }

    // block reduce
#pragma unroll
    for (int off = 16; off; off >>= 1) e += __shfl_down_sync(0xffffffffu, e, off);
    float* wsum = misc + 64;
    if ((tid & 31) == 0) wsum[tid >> 5] = e;
    __syncthreads();
    __shared__ int s_last;
    if (tid == 0) {
        float v = wsum[0]+wsum[1]+wsum[2]+wsum[3]+wsum[4]+wsum[5]+wsum[6]+wsum[7];
        g_partials[(b*16 + by)*16 + bx] = v;
        __threadfence();
        int old = atomicAdd(&g_done, 1);
        s_last = (old == NBLK - 1);
    }
    __syncthreads();

    if (s_last) {
        double acc = 0.0;
        for (int i = tid; i < NBLK; i += 256) acc += (double)g_partials[i];
        double* sh = (double*)sm;
        sh[tid] = acc;
        __syncthreads();
        for (int s2 = 128; s2; s2 >>= 1) {
            if (tid < s2) sh[tid] += sh[tid + s2];
            __syncthreads();
        }
        if (tid == 0) {
            out[0] = (float)(sh[0] / (double)NPIX);
            g_done = 0;
        }
    }
}

// ---------------------------------------------------------------------------
extern "C" void kernel_launch(void* const* d_in, const int* in_sizes, int n_in,
                              void* d_out, int out_size) {
    const float* x     = (const float*)d_in[0];
    const int*   t     = (const int*)  d_in[1];
    const float* W1    = (const float*)d_in[2];
    const float* b1    = (const float*)d_in[3];
    const float* tw    = (const float*)d_in[4];
    const float* W2    = (const float*)d_in[5];
    const float* b2    = (const float*)d_in[6];
    const float* sched = (const float*)d_in[7];

    cudaFuncSetAttribute(blur_kernel,
                         cudaFuncAttributeMaxDynamicSharedMemorySize, BLUR_SMEM);
    blur_kernel<<<dim3(NH/32, NB*NC), 256, BLUR_SMEM>>>(x, t, sched);

    cudaFuncSetAttribute(conv_loss_kernel,
                         cudaFuncAttributeMaxDynamicSharedMemorySize, CONV_SMEM);
    conv_loss_kernel<<<dim3(NW/TX, NH/TY, NB), 256, CONV_SMEM>>>(
        x, t, W1, b1, tw, W2, b2, (float*)d_out);
}